// round 8
// baseline (speedup 1.0000x reference)
#include <cuda_runtime.h>

#define DI static __device__ __forceinline__
typedef unsigned long long ull;

namespace {
constexpr int B = 2, S = 512, H = 128, A = 7;
constexpr int BS = B * S;
constexpr float LOG2E = 1.4426950408889634f;
constexpr float LN2   = 0.6931471805599453f;
constexpr float TK0   = 0.7978845608028654f;          // sqrt(2/pi)
constexpr float TK1   = TK0 * 0.044715f;
constexpr float GK0   = -2.0f * LOG2E * TK0;          // sigmoid-form consts (action head)
constexpr float GK1   = GK0 * 0.044715f;
constexpr float EPS   = 1e-5f;
}

// scratch: 0 = action pre, 2 = hd_left, 4 = hd_right
__device__ __align__(16) float g_pre[5][BS * H];
// hv transposed, channel-pair-major: g_hvT[head][q2][b*S + j] = float4(ch 4q2..4q2+3 of row j)
__device__ __align__(16) float4 g_hvT[2][H / 4][BS];
__device__ float g_logits[BS * A];

DI float ex2a(float x){ float y; asm("ex2.approx.ftz.f32 %0, %1;" : "=f"(y) : "f"(x)); return y; }
DI float rcpa(float x){ float y; asm("rcp.approx.ftz.f32 %0, %1;" : "=f"(y) : "f"(x)); return y; }
DI float lg2a(float x){ float y; asm("lg2.approx.ftz.f32 %0, %1;" : "=f"(y) : "f"(x)); return y; }
DI float rsqa(float x){ float y; asm("rsqrt.approx.ftz.f32 %0, %1;" : "=f"(y) : "f"(x)); return y; }
DI float tanha(float x){ float y; asm("tanh.approx.f32 %0, %1;" : "=f"(y) : "f"(x)); return y; }

// ---- packed f32x2 helpers (sm_103a) ----
DI ull pk2(float x, float y){ ull r; asm("mov.b64 %0, {%1, %2};" : "=l"(r) : "f"(x), "f"(y)); return r; }
DI void upk2(ull v, float& x, float& y){ asm("mov.b64 {%0, %1}, %2;" : "=f"(x), "=f"(y) : "l"(v)); }
DI ull add2(ull a, ull b){ ull r; asm("add.rn.f32x2 %0, %1, %2;" : "=l"(r) : "l"(a), "l"(b)); return r; }
DI ull mul2(ull a, ull b){ ull r; asm("mul.rn.f32x2 %0, %1, %2;" : "=l"(r) : "l"(a), "l"(b)); return r; }
DI ull fma2(ull a, ull b, ull c){ ull r; asm("fma.rn.f32x2 %0, %1, %2, %3;" : "=l"(r) : "l"(a), "l"(b), "l"(c)); return r; }

// exact-ish gelu (sigmoid form) for the action head
DI float gelu_f(float x){
  float x2 = x * x;
  float w  = x * fmaf(GK1, x2, GK0);
  return x * rcpa(1.0f + ex2a(w));
}

DI float wredmax(float v){
  #pragma unroll
  for (int o = 16; o; o >>= 1) v = fmaxf(v, __shfl_xor_sync(0xffffffffu, v, o));
  return v;
}
DI float wredsum(float v){
  #pragma unroll
  for (int o = 16; o; o >>= 1) v += __shfl_xor_sync(0xffffffffu, v, o);
  return v;
}

// ---------------- P1: five [1024,128]@[128,128]+bias GEMMs ----------------
// 8-row CTAs (640 total) for latency coverage. m=1,3: transposed store to g_hvT.
__global__ void __launch_bounds__(128) k_gemm(
    const float* __restrict__ x,
    const float* __restrict__ W0, const float* __restrict__ Bi0,
    const float* __restrict__ W1, const float* __restrict__ Bi1,
    const float* __restrict__ W2, const float* __restrict__ Bi2,
    const float* __restrict__ W3, const float* __restrict__ Bi3,
    const float* __restrict__ W4, const float* __restrict__ Bi4)
{
  __shared__ float xs[8][H];
  __shared__ __align__(16) float4 st[8][33];
  int m = blockIdx.y;
  const float* W = W0; const float* bias = Bi0;
  if      (m == 1){ W = W1; bias = Bi1; }
  else if (m == 2){ W = W2; bias = Bi2; }
  else if (m == 3){ W = W3; bias = Bi3; }
  else if (m == 4){ W = W4; bias = Bi4; }

  int r0 = blockIdx.x * 8;
  int t  = threadIdx.x;
  #pragma unroll
  for (int r = 0; r < 8; ++r) xs[r][t] = x[(r0 + r) * H + t];
  __syncthreads();

  int rt = (t >> 5) * 2;       // 2 rows per warp
  int c0 = (t & 31) * 4;
  int lane = t & 31;
  float4 bv = *(const float4*)&bias[c0];
  float acc[2][4];
  #pragma unroll
  for (int i = 0; i < 2; ++i){ acc[i][0]=bv.x; acc[i][1]=bv.y; acc[i][2]=bv.z; acc[i][3]=bv.w; }

  #pragma unroll 8
  for (int h = 0; h < H; ++h) {
    float4 w4 = *(const float4*)&W[h * H + c0];
    float xv0 = xs[rt][h], xv1 = xs[rt + 1][h];
    acc[0][0] = fmaf(xv0, w4.x, acc[0][0]);
    acc[0][1] = fmaf(xv0, w4.y, acc[0][1]);
    acc[0][2] = fmaf(xv0, w4.z, acc[0][2]);
    acc[0][3] = fmaf(xv0, w4.w, acc[0][3]);
    acc[1][0] = fmaf(xv1, w4.x, acc[1][0]);
    acc[1][1] = fmaf(xv1, w4.y, acc[1][1]);
    acc[1][2] = fmaf(xv1, w4.z, acc[1][2]);
    acc[1][3] = fmaf(xv1, w4.w, acc[1][3]);
  }

  if (m == 1 || m == 3) {
    int hh = (m == 1) ? 0 : 1;
    #pragma unroll
    for (int i = 0; i < 2; ++i){
      float4 o; o.x=acc[i][0]; o.y=acc[i][1]; o.z=acc[i][2]; o.w=acc[i][3];
      st[rt + i][lane] = o;
    }
    __syncthreads();
    #pragma unroll
    for (int k = 0; k < 2; ++k) {
      int idx = t + k * 128;
      int q2 = idx >> 3, r = idx & 7;
      g_hvT[hh][q2][r0 + r] = st[r][q2];
    }
  } else {
    float* out = g_pre[m];
    #pragma unroll
    for (int i = 0; i < 2; ++i){
      float4 o; o.x=acc[i][0]; o.y=acc[i][1]; o.z=acc[i][2]; o.w=acc[i][3];
      *(float4*)&out[(r0 + rt + i) * H + c0] = o;
    }
  }
}

// ---------------- P2: action head rows: GeLU -> LN -> @aw2 + ab2 ----------------
__global__ void __launch_bounds__(128) k_action(
    const float* __restrict__ lng, const float* __restrict__ lnb,
    const float* __restrict__ aw2, const float* __restrict__ ab2)
{
  int row = blockIdx.x;
  int h   = threadIdx.x;
  float y = gelu_f(g_pre[0][row * H + h]);

  __shared__ float red1[4], red2[4], ys[H];
  float s1 = wredsum(y);
  float s2 = wredsum(y * y);
  int wid = h >> 5;
  if ((h & 31) == 0){ red1[wid] = s1; red2[wid] = s2; }
  __syncthreads();
  float t1 = red1[0] + red1[1] + red1[2] + red1[3];
  float t2 = red2[0] + red2[1] + red2[2] + red2[3];
  float mean = t1 * (1.0f / H);
  float var  = fmaf(-mean, mean, t2 * (1.0f / H));
  float rstd = rsqa(var + EPS);
  ys[h] = fmaf((y - mean) * rstd, lng[h], lnb[h]);
  __syncthreads();
  if (h < A){
    float acc = ab2[h];
    #pragma unroll 8
    for (int k = 0; k < H; ++k) acc = fmaf(ys[k], aw2[k * A + h], acc);
    g_logits[row * A + h] = acc;
  }
}

// ---------------- P3: action log_softmax over dim 1 (sequence) ----------------
__global__ void __launch_bounds__(512) k_actsm(float* __restrict__ out)
{
  int b = blockIdx.x / A, a = blockIdx.x % A;
  int s = threadIdx.x;
  float v = g_logits[(b * S + s) * A + a];

  __shared__ float red[16];
  __shared__ float bmax_s, bsum_s;
  int wid = s >> 5, lane = s & 31;

  float m = wredmax(v);
  if (lane == 0) red[wid] = m;
  __syncthreads();
  if (s < 32){
    float tt = (s < 16) ? red[s] : -3.4e38f;
    tt = wredmax(tt);
    if (s == 0) bmax_s = tt;
  }
  __syncthreads();
  float bmax = bmax_s;
  float e = ex2a((v - bmax) * LOG2E);
  float sm = wredsum(e);
  __syncthreads();
  if (lane == 0) red[wid] = sm;
  __syncthreads();
  if (s < 32){
    float tt = (s < 16) ? red[s] : 0.0f;
    tt = wredsum(tt);
    if (s == 0) bsum_s = tt;
  }
  __syncthreads();
  out[(b * S + s) * A + a] = v - bmax - lg2a(bsum_s) * LN2;
}

// ---------------- P4: pointer heads (f32x2 + HW tanh, transposed hv LDG) -----
// grid (S/2, B, 2) = 1024 CTAs, block 256 = 2 i-rows x 4 j-quarter groups.
__global__ void __launch_bounds__(256, 5) k_ptr(
    const float* __restrict__ lg, const float* __restrict__ lb,
    const float* __restrict__ lpw, const float* __restrict__ lpb,
    const float* __restrict__ rg, const float* __restrict__ rb,
    const float* __restrict__ rpw, const float* __restrict__ rpb,
    float* __restrict__ out)
{
  int head = blockIdx.z, b = blockIdx.y;
  int i0 = blockIdx.x * 2;
  const float* gv = head ? rg  : lg;
  const float* bv = head ? rb  : lb;
  const float* pw = head ? rpw : lpw;
  const float* pb = head ? rpb : lpb;
  const float* hd = g_pre[2 + 2 * head] + b * S * H;   // indexed by i

  __shared__ __align__(16) float hds[2][H];
  __shared__ __align__(16) float wgh[H];
  __shared__ float redc[4][2];
  __shared__ float cc2[2];
  __shared__ float gmaxs[4][2], gsums[4][2];

  int tid  = threadIdx.x;
  int wid  = tid >> 5, lane = tid & 31;
  int g    = wid & 3;         // j-quarter group (0..3)
  int ir   = wid >> 2;        // i-row within CTA (0..1)

  // folded weights: wgh = g*pw ; c1 = sum(g*pw) ; c2 = sum(b*pw) + pb
  if (tid < 128) {
    float p  = pw[tid];
    float wg = gv[tid] * p;
    float tb = bv[tid] * p;
    wgh[tid] = wg;
    float r1 = wredsum(wg), r2 = wredsum(tb);
    if (lane == 0){ redc[wid][0] = r1; redc[wid][1] = r2; }
  }
  for (int idx = tid; idx < 2 * H; idx += 256)
    hds[idx >> 7][idx & (H - 1)] = hd[(i0 + (idx >> 7)) * H + (idx & (H - 1))];
  __syncthreads();
  if (tid == 0){
    cc2[0] = redc[0][0] + redc[1][0] + redc[2][0] + redc[3][0];
    cc2[1] = redc[0][1] + redc[1][1] + redc[2][1] + redc[3][1] + pb[0];
  }
  __syncthreads();
  float c1 = cc2[0], c2 = cc2[1];

  const ull K0p = pk2(TK0, TK0);
  const ull K1p = pk2(TK1, TK1);
  const ull HLp = pk2(0.5f, 0.5f);

  float sc[4];

  #pragma unroll
  for (int tile = 0; tile < 4; ++tile) {
    int jb = (g * 4 + tile) * 32;
    const ulonglong2* ap = (const ulonglong2*)&g_hvT[head][0][b * S + jb + lane];
    const ulonglong2* dr = (const ulonglong2*)&hds[ir][0];
    const ulonglong2* wr = (const ulonglong2*)&wgh[0];

    ull s1 = 0, s2 = 0, s3 = 0;
    #pragma unroll 4
    for (int q2 = 0; q2 < 32; ++q2) {
      ulonglong2 a2 = ap[q2 * BS];
      ulonglong2 d2 = dr[q2];
      ulonglong2 w2 = wr[q2];
      #pragma unroll
      for (int half = 0; half < 2; ++half) {
        ull a = half ? a2.y : a2.x;
        ull d = half ? d2.y : d2.x;
        ull w = half ? w2.y : w2.x;
        ull x  = add2(a, d);
        ull x2 = mul2(x, x);
        ull p  = fma2(K1p, x2, K0p);
        ull u  = mul2(x, p);
        float u0f, u1f; upk2(u, u0f, u1f);
        ull tt = pk2(tanha(u0f), tanha(u1f));
        ull xh = mul2(x, HLp);
        ull y  = fma2(xh, tt, xh);
        s1 = add2(s1, y);
        s2 = fma2(y, y, s2);
        s3 = fma2(y, w, s3);
      }
    }
    float a0,a1,b0,b1,d0,d1;
    upk2(s1, a0, a1); upk2(s2, b0, b1); upk2(s3, d0, d1);
    float t1 = a0 + a1, t2 = b0 + b1, t3 = d0 + d1;
    float mean = t1 * (1.0f / H);
    float var  = fmaf(-mean, mean, t2 * (1.0f / H));
    float rstd = rsqa(var + EPS);
    sc[tile] = fmaf(rstd, fmaf(-mean, c1, t3), c2);
  }

  // log_softmax over j: combine the 4 j-quarter groups per i-row
  float lmax = fmaxf(fmaxf(sc[0], sc[1]), fmaxf(sc[2], sc[3]));
  lmax = wredmax(lmax);
  if (lane == 0) gmaxs[g][ir] = lmax;
  __syncthreads();
  float m = fmaxf(fmaxf(gmaxs[0][ir], gmaxs[1][ir]), fmaxf(gmaxs[2][ir], gmaxs[3][ir]));
  float lsum = 0.f;
  #pragma unroll
  for (int k = 0; k < 4; ++k) lsum += ex2a((sc[k] - m) * LOG2E);
  lsum = wredsum(lsum);
  if (lane == 0) gsums[g][ir] = lsum;
  __syncthreads();
  float lse = lg2a(gsums[0][ir] + gsums[1][ir] + gsums[2][ir] + gsums[3][ir]) * LN2;

  float* orow = out + B * S * A + head * (B * S * S) + (b * S + i0 + ir) * S + g * 128;
  #pragma unroll
  for (int k = 0; k < 4; ++k) orow[k * 32 + lane] = sc[k] - m - lse;
}

extern "C" void kernel_launch(void* const* d_in, const int* in_sizes, int n_in,
                              void* d_out, int out_size)
{
  (void)in_sizes; (void)n_in; (void)out_size;
  const float* hiddens = (const float*)d_in[0];
  const float* aw1     = (const float*)d_in[1];
  const float* ab1     = (const float*)d_in[2];
  const float* a_ln_g  = (const float*)d_in[3];
  const float* a_ln_b  = (const float*)d_in[4];
  const float* aw2     = (const float*)d_in[5];
  const float* ab2     = (const float*)d_in[6];
  const float* lhid_w  = (const float*)d_in[7];
  const float* lhid_b  = (const float*)d_in[8];
  const float* lhead_w = (const float*)d_in[9];
  const float* lhead_b = (const float*)d_in[10];
  const float* l_ln_g  = (const float*)d_in[11];
  const float* l_ln_b  = (const float*)d_in[12];
  const float* l_proj_w= (const float*)d_in[13];
  const float* l_proj_b= (const float*)d_in[14];
  const float* rhid_w  = (const float*)d_in[15];
  const float* rhid_b  = (const float*)d_in[16];
  const float* rhead_w = (const float*)d_in[17];
  const float* rhead_b = (const float*)d_in[18];
  const float* r_ln_g  = (const float*)d_in[19];
  const float* r_ln_b  = (const float*)d_in[20];
  const float* r_proj_w= (const float*)d_in[21];
  const float* r_proj_b= (const float*)d_in[22];
  float* out = (float*)d_out;

  k_gemm<<<dim3(BS / 8, 5), 128>>>(hiddens,
      aw1, ab1, lhid_w, lhid_b, lhead_w, lhead_b, rhid_w, rhid_b, rhead_w, rhead_b);
  k_action<<<BS, 128>>>(a_ln_g, a_ln_b, aw2, ab2);
  k_actsm<<<B * A, 512>>>(out);
  k_ptr<<<dim3(S / 2, B, 2), 256>>>(l_ln_g, l_ln_b, l_proj_w, l_proj_b,
                                    r_ln_g, r_ln_b, r_proj_w, r_proj_b, out);
}

// round 9
// speedup vs baseline: 1.0979x; 1.0979x over previous
#include <cuda_runtime.h>

#define DI static __device__ __forceinline__
typedef unsigned long long ull;

namespace {
constexpr int B = 2, S = 512, H = 128, A = 7;
constexpr int BS = B * S;
constexpr float LOG2E = 1.4426950408889634f;
constexpr float LN2   = 0.6931471805599453f;
constexpr float TK0   = 0.7978845608028654f;          // sqrt(2/pi)
constexpr float TK1   = TK0 * 0.044715f;
constexpr float GK0   = -2.0f * LOG2E * TK0;          // sigmoid-form consts (action head)
constexpr float GK1   = GK0 * 0.044715f;
constexpr float EPS   = 1e-5f;
}

// scratch: 0 = action pre, 2 = hd_left, 4 = hd_right
__device__ __align__(16) float g_pre[5][BS * H];
// hv transposed, channel-pair-major: g_hvT[head][q2][b*S + j] = float4(ch 4q2..4q2+3 of row j)
__device__ __align__(16) float4 g_hvT[2][H / 4][BS];
__device__ float g_logits[BS * A];

DI float ex2a(float x){ float y; asm("ex2.approx.ftz.f32 %0, %1;" : "=f"(y) : "f"(x)); return y; }
DI float rcpa(float x){ float y; asm("rcp.approx.ftz.f32 %0, %1;" : "=f"(y) : "f"(x)); return y; }
DI float lg2a(float x){ float y; asm("lg2.approx.ftz.f32 %0, %1;" : "=f"(y) : "f"(x)); return y; }
DI float rsqa(float x){ float y; asm("rsqrt.approx.ftz.f32 %0, %1;" : "=f"(y) : "f"(x)); return y; }
DI float tanha(float x){ float y; asm("tanh.approx.f32 %0, %1;" : "=f"(y) : "f"(x)); return y; }

// ---- packed f32x2 helpers (sm_103a) ----
DI ull pk2(float x, float y){ ull r; asm("mov.b64 %0, {%1, %2};" : "=l"(r) : "f"(x), "f"(y)); return r; }
DI void upk2(ull v, float& x, float& y){ asm("mov.b64 {%0, %1}, %2;" : "=f"(x), "=f"(y) : "l"(v)); }
DI ull add2(ull a, ull b){ ull r; asm("add.rn.f32x2 %0, %1, %2;" : "=l"(r) : "l"(a), "l"(b)); return r; }
DI ull mul2(ull a, ull b){ ull r; asm("mul.rn.f32x2 %0, %1, %2;" : "=l"(r) : "l"(a), "l"(b)); return r; }
DI ull fma2(ull a, ull b, ull c){ ull r; asm("fma.rn.f32x2 %0, %1, %2, %3;" : "=l"(r) : "l"(a), "l"(b), "l"(c)); return r; }

// exact-ish gelu (sigmoid form) for the action head
DI float gelu_f(float x){
  float x2 = x * x;
  float w  = x * fmaf(GK1, x2, GK0);
  return x * rcpa(1.0f + ex2a(w));
}

DI float wredmax(float v){
  #pragma unroll
  for (int o = 16; o; o >>= 1) v = fmaxf(v, __shfl_xor_sync(0xffffffffu, v, o));
  return v;
}
DI float wredsum(float v){
  #pragma unroll
  for (int o = 16; o; o >>= 1) v += __shfl_xor_sync(0xffffffffu, v, o);
  return v;
}

// ---------------- P1: five [1024,128]@[128,128]+bias GEMMs ----------------
// 8-row CTAs (640 total). m=1,3: transposed coalesced store to g_hvT.
__global__ void __launch_bounds__(128) k_gemm(
    const float* __restrict__ x,
    const float* __restrict__ W0, const float* __restrict__ Bi0,
    const float* __restrict__ W1, const float* __restrict__ Bi1,
    const float* __restrict__ W2, const float* __restrict__ Bi2,
    const float* __restrict__ W3, const float* __restrict__ Bi3,
    const float* __restrict__ W4, const float* __restrict__ Bi4)
{
  __shared__ float xs[8][H];
  __shared__ __align__(16) float4 st[8][33];
  int m = blockIdx.y;
  const float* W = W0; const float* bias = Bi0;
  if      (m == 1){ W = W1; bias = Bi1; }
  else if (m == 2){ W = W2; bias = Bi2; }
  else if (m == 3){ W = W3; bias = Bi3; }
  else if (m == 4){ W = W4; bias = Bi4; }

  int r0 = blockIdx.x * 8;
  int t  = threadIdx.x;
  #pragma unroll
  for (int r = 0; r < 8; ++r) xs[r][t] = x[(r0 + r) * H + t];
  __syncthreads();

  int rt = (t >> 5) * 2;       // 2 rows per warp
  int c0 = (t & 31) * 4;
  int lane = t & 31;
  float4 bv = *(const float4*)&bias[c0];
  float acc[2][4];
  #pragma unroll
  for (int i = 0; i < 2; ++i){ acc[i][0]=bv.x; acc[i][1]=bv.y; acc[i][2]=bv.z; acc[i][3]=bv.w; }

  #pragma unroll 8
  for (int h = 0; h < H; ++h) {
    float4 w4 = *(const float4*)&W[h * H + c0];
    float xv0 = xs[rt][h], xv1 = xs[rt + 1][h];
    acc[0][0] = fmaf(xv0, w4.x, acc[0][0]);
    acc[0][1] = fmaf(xv0, w4.y, acc[0][1]);
    acc[0][2] = fmaf(xv0, w4.z, acc[0][2]);
    acc[0][3] = fmaf(xv0, w4.w, acc[0][3]);
    acc[1][0] = fmaf(xv1, w4.x, acc[1][0]);
    acc[1][1] = fmaf(xv1, w4.y, acc[1][1]);
    acc[1][2] = fmaf(xv1, w4.z, acc[1][2]);
    acc[1][3] = fmaf(xv1, w4.w, acc[1][3]);
  }

  if (m == 1 || m == 3) {
    int hh = (m == 1) ? 0 : 1;
    #pragma unroll
    for (int i = 0; i < 2; ++i){
      float4 o; o.x=acc[i][0]; o.y=acc[i][1]; o.z=acc[i][2]; o.w=acc[i][3];
      st[rt + i][lane] = o;
    }
    __syncthreads();
    #pragma unroll
    for (int k = 0; k < 2; ++k) {
      int idx = t + k * 128;
      int q2 = idx >> 3, r = idx & 7;
      g_hvT[hh][q2][r0 + r] = st[r][q2];
    }
  } else {
    float* out = g_pre[m];
    #pragma unroll
    for (int i = 0; i < 2; ++i){
      float4 o; o.x=acc[i][0]; o.y=acc[i][1]; o.z=acc[i][2]; o.w=acc[i][3];
      *(float4*)&out[(r0 + rt + i) * H + c0] = o;
    }
  }
}

// ---------------- P2: action head rows: GeLU -> LN -> @aw2 + ab2 ----------------
__global__ void __launch_bounds__(128) k_action(
    const float* __restrict__ lng, const float* __restrict__ lnb,
    const float* __restrict__ aw2, const float* __restrict__ ab2)
{
  int row = blockIdx.x;
  int h   = threadIdx.x;
  float y = gelu_f(g_pre[0][row * H + h]);

  __shared__ float red1[4], red2[4], ys[H];
  float s1 = wredsum(y);
  float s2 = wredsum(y * y);
  int wid = h >> 5;
  if ((h & 31) == 0){ red1[wid] = s1; red2[wid] = s2; }
  __syncthreads();
  float t1 = red1[0] + red1[1] + red1[2] + red1[3];
  float t2 = red2[0] + red2[1] + red2[2] + red2[3];
  float mean = t1 * (1.0f / H);
  float var  = fmaf(-mean, mean, t2 * (1.0f / H));
  float rstd = rsqa(var + EPS);
  ys[h] = fmaf((y - mean) * rstd, lng[h], lnb[h]);
  __syncthreads();
  if (h < A){
    float acc = ab2[h];
    #pragma unroll 8
    for (int k = 0; k < H; ++k) acc = fmaf(ys[k], aw2[k * A + h], acc);
    g_logits[row * A + h] = acc;
  }
}

// ---------------- P3: action log_softmax over dim 1 (sequence) ----------------
__global__ void __launch_bounds__(512) k_actsm(float* __restrict__ out)
{
  int b = blockIdx.x / A, a = blockIdx.x % A;
  int s = threadIdx.x;
  float v = g_logits[(b * S + s) * A + a];

  __shared__ float red[16];
  __shared__ float bmax_s, bsum_s;
  int wid = s >> 5, lane = s & 31;

  float m = wredmax(v);
  if (lane == 0) red[wid] = m;
  __syncthreads();
  if (s < 32){
    float tt = (s < 16) ? red[s] : -3.4e38f;
    tt = wredmax(tt);
    if (s == 0) bmax_s = tt;
  }
  __syncthreads();
  float bmax = bmax_s;
  float e = ex2a((v - bmax) * LOG2E);
  float sm = wredsum(e);
  __syncthreads();
  if (lane == 0) red[wid] = sm;
  __syncthreads();
  if (s < 32){
    float tt = (s < 16) ? red[s] : 0.0f;
    tt = wredsum(tt);
    if (s == 0) bsum_s = tt;
  }
  __syncthreads();
  out[(b * S + s) * A + a] = v - bmax - lg2a(bsum_s) * LN2;
}

// ---------------- P4: pointer heads (f32x2 + HW tanh, 2 i-rows/warp) ---------
// grid (S/4, B, 2) = 512 CTAs, block 256 = 4 j-quarter groups x 2 i-pairs.
// Warp: 2 i-rows x 128 j; each hv LDG.128 feeds both rows (halved load traffic).
// z-form gelu: accumulate z = x*t + x (=2y); fold 0.5/0.25 into final scalars.
__global__ void __launch_bounds__(256, 4) k_ptr(
    const float* __restrict__ lg, const float* __restrict__ lb,
    const float* __restrict__ lpw, const float* __restrict__ lpb,
    const float* __restrict__ rg, const float* __restrict__ rb,
    const float* __restrict__ rpw, const float* __restrict__ rpb,
    float* __restrict__ out)
{
  int head = blockIdx.z, b = blockIdx.y;
  int i0 = blockIdx.x * 4;
  const float* gv = head ? rg  : lg;
  const float* bv = head ? rb  : lb;
  const float* pw = head ? rpw : lpw;
  const float* pb = head ? rpb : lpb;
  const float* hd = g_pre[2 + 2 * head] + b * S * H;   // indexed by i

  __shared__ __align__(16) float hds[4][H];
  __shared__ __align__(16) float wgh[H];
  __shared__ float redc[4][2];
  __shared__ float cc2[2];
  __shared__ float gmaxs[4][4], gsums[4][4];

  int tid  = threadIdx.x;
  int wid  = tid >> 5, lane = tid & 31;
  int g    = wid & 3;         // j-quarter group (0..3)
  int ip   = wid >> 2;        // i-pair (0..1); rows 2*ip, 2*ip+1

  // folded weights: wgh = g*pw ; c1 = sum(g*pw) ; c2 = sum(b*pw) + pb
  if (tid < 128) {
    float p  = pw[tid];
    float wg = gv[tid] * p;
    float tb = bv[tid] * p;
    wgh[tid] = wg;
    float r1 = wredsum(wg), r2 = wredsum(tb);
    if (lane == 0){ redc[wid][0] = r1; redc[wid][1] = r2; }
  }
  for (int idx = tid; idx < 4 * H; idx += 256)
    hds[idx >> 7][idx & (H - 1)] = hd[(i0 + (idx >> 7)) * H + (idx & (H - 1))];
  __syncthreads();
  if (tid == 0){
    cc2[0] = redc[0][0] + redc[1][0] + redc[2][0] + redc[3][0];
    cc2[1] = redc[0][1] + redc[1][1] + redc[2][1] + redc[3][1] + pb[0];
  }
  __syncthreads();
  float c1 = cc2[0], c2 = cc2[1];

  const ull K0p = pk2(TK0, TK0);
  const ull K1p = pk2(TK1, TK1);

  float scA[4], scB[4];

  #pragma unroll
  for (int tile = 0; tile < 4; ++tile) {
    int jb = (g * 4 + tile) * 32;
    const ulonglong2* ap  = (const ulonglong2*)&g_hvT[head][0][b * S + jb + lane];
    const ulonglong2* drA = (const ulonglong2*)&hds[2 * ip][0];
    const ulonglong2* drB = (const ulonglong2*)&hds[2 * ip + 1][0];
    const ulonglong2* wr  = (const ulonglong2*)&wgh[0];

    ull sA1 = 0, sA2 = 0, sA3 = 0;
    ull sB1 = 0, sB2 = 0, sB3 = 0;
    #pragma unroll 8
    for (int q2 = 0; q2 < 32; ++q2) {
      ulonglong2 a2  = ap[q2 * BS];
      ulonglong2 dA2 = drA[q2];
      ulonglong2 dB2 = drB[q2];
      ulonglong2 w2  = wr[q2];
      #pragma unroll
      for (int half = 0; half < 2; ++half) {
        ull a  = half ? a2.y  : a2.x;
        ull w  = half ? w2.y  : w2.x;
        ull dA = half ? dA2.y : dA2.x;
        ull dB = half ? dB2.y : dB2.x;
        // row A
        {
          ull x  = add2(a, dA);
          ull x2 = mul2(x, x);
          ull p  = fma2(K1p, x2, K0p);
          ull u  = mul2(x, p);
          float u0f, u1f; upk2(u, u0f, u1f);
          ull t  = pk2(tanha(u0f), tanha(u1f));
          ull z  = fma2(x, t, x);          // z = 2*gelu(x)
          sA1 = add2(sA1, z);
          sA2 = fma2(z, z, sA2);
          sA3 = fma2(z, w, sA3);
        }
        // row B
        {
          ull x  = add2(a, dB);
          ull x2 = mul2(x, x);
          ull p  = fma2(K1p, x2, K0p);
          ull u  = mul2(x, p);
          float u0f, u1f; upk2(u, u0f, u1f);
          ull t  = pk2(tanha(u0f), tanha(u1f));
          ull z  = fma2(x, t, x);
          sB1 = add2(sB1, z);
          sB2 = fma2(z, z, sB2);
          sB3 = fma2(z, w, sB3);
        }
      }
    }
    float a0,a1,q0,q1,d0,d1;
    upk2(sA1, a0, a1); upk2(sA2, q0, q1); upk2(sA3, d0, d1);
    {
      float t1 = a0 + a1, t2 = q0 + q1, t3 = d0 + d1;
      float mean = t1 * (0.5f / H);                       // sum(y)/H, y = z/2
      float var  = fmaf(-mean, mean, t2 * (0.25f / H));
      float rstd = rsqa(var + EPS);
      scA[tile] = fmaf(rstd, fmaf(-mean, c1, 0.5f * t3), c2);
    }
    upk2(sB1, a0, a1); upk2(sB2, q0, q1); upk2(sB3, d0, d1);
    {
      float t1 = a0 + a1, t2 = q0 + q1, t3 = d0 + d1;
      float mean = t1 * (0.5f / H);
      float var  = fmaf(-mean, mean, t2 * (0.25f / H));
      float rstd = rsqa(var + EPS);
      scB[tile] = fmaf(rstd, fmaf(-mean, c1, 0.5f * t3), c2);
    }
  }

  // log_softmax over j: combine 4 j-quarter groups per i-row (2 rows per warp)
  int rA = 2 * ip, rB = 2 * ip + 1;
  float lmA = fmaxf(fmaxf(scA[0], scA[1]), fmaxf(scA[2], scA[3]));
  float lmB = fmaxf(fmaxf(scB[0], scB[1]), fmaxf(scB[2], scB[3]));
  lmA = wredmax(lmA);
  lmB = wredmax(lmB);
  if (lane == 0){ gmaxs[g][rA] = lmA; gmaxs[g][rB] = lmB; }
  __syncthreads();
  float mA = fmaxf(fmaxf(gmaxs[0][rA], gmaxs[1][rA]), fmaxf(gmaxs[2][rA], gmaxs[3][rA]));
  float mB = fmaxf(fmaxf(gmaxs[0][rB], gmaxs[1][rB]), fmaxf(gmaxs[2][rB], gmaxs[3][rB]));
  float lsA = 0.f, lsB = 0.f;
  #pragma unroll
  for (int k = 0; k < 4; ++k){
    lsA += ex2a((scA[k] - mA) * LOG2E);
    lsB += ex2a((scB[k] - mB) * LOG2E);
  }
  lsA = wredsum(lsA);
  lsB = wredsum(lsB);
  if (lane == 0){ gsums[g][rA] = lsA; gsums[g][rB] = lsB; }
  __syncthreads();
  float lseA = lg2a(gsums[0][rA] + gsums[1][rA] + gsums[2][rA] + gsums[3][rA]) * LN2;
  float lseB = lg2a(gsums[0][rB] + gsums[1][rB] + gsums[2][rB] + gsums[3][rB]) * LN2;

  float* obase = out + B * S * A + head * (B * S * S);
  float* orA = obase + (b * S + i0 + rA) * S + g * 128;
  float* orB = obase + (b * S + i0 + rB) * S + g * 128;
  #pragma unroll
  for (int k = 0; k < 4; ++k){
    orA[k * 32 + lane] = scA[k] - mA - lseA;
    orB[k * 32 + lane] = scB[k] - mB - lseB;
  }
}

extern "C" void kernel_launch(void* const* d_in, const int* in_sizes, int n_in,
                              void* d_out, int out_size)
{
  (void)in_sizes; (void)n_in; (void)out_size;
  const float* hiddens = (const float*)d_in[0];
  const float* aw1     = (const float*)d_in[1];
  const float* ab1     = (const float*)d_in[2];
  const float* a_ln_g  = (const float*)d_in[3];
  const float* a_ln_b  = (const float*)d_in[4];
  const float* aw2     = (const float*)d_in[5];
  const float* ab2     = (const float*)d_in[6];
  const float* lhid_w  = (const float*)d_in[7];
  const float* lhid_b  = (const float*)d_in[8];
  const float* lhead_w = (const float*)d_in[9];
  const float* lhead_b = (const float*)d_in[10];
  const float* l_ln_g  = (const float*)d_in[11];
  const float* l_ln_b  = (const float*)d_in[12];
  const float* l_proj_w= (const float*)d_in[13];
  const float* l_proj_b= (const float*)d_in[14];
  const float* rhid_w  = (const float*)d_in[15];
  const float* rhid_b  = (const float*)d_in[16];
  const float* rhead_w = (const float*)d_in[17];
  const float* rhead_b = (const float*)d_in[18];
  const float* r_ln_g  = (const float*)d_in[19];
  const float* r_ln_b  = (const float*)d_in[20];
  const float* r_proj_w= (const float*)d_in[21];
  const float* r_proj_b= (const float*)d_in[22];
  float* out = (float*)d_out;

  k_gemm<<<dim3(BS / 8, 5), 128>>>(hiddens,
      aw1, ab1, lhid_w, lhid_b, lhead_w, lhead_b, rhid_w, rhid_b, rhead_w, rhead_b);
  k_action<<<BS, 128>>>(a_ln_g, a_ln_b, aw2, ab2);
  k_actsm<<<B * A, 512>>>(out);
  k_ptr<<<dim3(S / 4, B, 2), 256>>>(l_ln_g, l_ln_b, l_proj_w, l_proj_b,
                                    r_ln_g, r_ln_b, r_proj_w, r_proj_b, out);
}

// round 10
// speedup vs baseline: 1.1074x; 1.0086x over previous
#include <cuda_runtime.h>

#define DI static __device__ __forceinline__
typedef unsigned long long ull;

namespace {
constexpr int B = 2, S = 512, H = 128, A = 7;
constexpr int BS = B * S;
constexpr float LOG2E = 1.4426950408889634f;
constexpr float LN2   = 0.6931471805599453f;
constexpr float TK0   = 0.7978845608028654f;          // sqrt(2/pi)
constexpr float TK1   = TK0 * 0.044715f;
constexpr float GK0   = -2.0f * LOG2E * TK0;          // sigmoid-form consts (action head)
constexpr float GK1   = GK0 * 0.044715f;
constexpr float EPS   = 1e-5f;
}

// scratch: 0 = action pre, 2 = hd_left, 4 = hd_right
__device__ __align__(16) float g_pre[5][BS * H];
// hv transposed, channel-pair-major: g_hvT[head][q2][b*S + j] = float4(ch 4q2..4q2+3 of row j)
__device__ __align__(16) float4 g_hvT[2][H / 4][BS];
__device__ float g_logits[BS * A];

DI float ex2a(float x){ float y; asm("ex2.approx.ftz.f32 %0, %1;" : "=f"(y) : "f"(x)); return y; }
DI float rcpa(float x){ float y; asm("rcp.approx.ftz.f32 %0, %1;" : "=f"(y) : "f"(x)); return y; }
DI float lg2a(float x){ float y; asm("lg2.approx.ftz.f32 %0, %1;" : "=f"(y) : "f"(x)); return y; }
DI float rsqa(float x){ float y; asm("rsqrt.approx.ftz.f32 %0, %1;" : "=f"(y) : "f"(x)); return y; }
DI float tanha(float x){ float y; asm("tanh.approx.f32 %0, %1;" : "=f"(y) : "f"(x)); return y; }

// ---- packed f32x2 helpers (sm_103a) ----
DI ull pk2(float x, float y){ ull r; asm("mov.b64 %0, {%1, %2};" : "=l"(r) : "f"(x), "f"(y)); return r; }
DI void upk2(ull v, float& x, float& y){ asm("mov.b64 {%0, %1}, %2;" : "=f"(x), "=f"(y) : "l"(v)); }
DI ull add2(ull a, ull b){ ull r; asm("add.rn.f32x2 %0, %1, %2;" : "=l"(r) : "l"(a), "l"(b)); return r; }
DI ull mul2(ull a, ull b){ ull r; asm("mul.rn.f32x2 %0, %1, %2;" : "=l"(r) : "l"(a), "l"(b)); return r; }
DI ull fma2(ull a, ull b, ull c){ ull r; asm("fma.rn.f32x2 %0, %1, %2, %3;" : "=l"(r) : "l"(a), "l"(b), "l"(c)); return r; }

// exact-ish gelu (sigmoid form) for the action head
DI float gelu_f(float x){
  float x2 = x * x;
  float w  = x * fmaf(GK1, x2, GK0);
  return x * rcpa(1.0f + ex2a(w));
}

DI float wredmax(float v){
  #pragma unroll
  for (int o = 16; o; o >>= 1) v = fmaxf(v, __shfl_xor_sync(0xffffffffu, v, o));
  return v;
}
DI float wredsum(float v){
  #pragma unroll
  for (int o = 16; o; o >>= 1) v += __shfl_xor_sync(0xffffffffu, v, o);
  return v;
}

// ---------------- P1: five [1024,128]@[128,128]+bias GEMMs ----------------
// 8-row CTAs (640 total). m=1,3: transposed coalesced store to g_hvT.
__global__ void __launch_bounds__(128) k_gemm(
    const float* __restrict__ x,
    const float* __restrict__ W0, const float* __restrict__ Bi0,
    const float* __restrict__ W1, const float* __restrict__ Bi1,
    const float* __restrict__ W2, const float* __restrict__ Bi2,
    const float* __restrict__ W3, const float* __restrict__ Bi3,
    const float* __restrict__ W4, const float* __restrict__ Bi4)
{
  __shared__ float xs[8][H];
  __shared__ __align__(16) float4 st[8][33];
  int m = blockIdx.y;
  const float* W = W0; const float* bias = Bi0;
  if      (m == 1){ W = W1; bias = Bi1; }
  else if (m == 2){ W = W2; bias = Bi2; }
  else if (m == 3){ W = W3; bias = Bi3; }
  else if (m == 4){ W = W4; bias = Bi4; }

  int r0 = blockIdx.x * 8;
  int t  = threadIdx.x;
  #pragma unroll
  for (int r = 0; r < 8; ++r) xs[r][t] = x[(r0 + r) * H + t];
  __syncthreads();

  int rt = (t >> 5) * 2;       // 2 rows per warp
  int c0 = (t & 31) * 4;
  int lane = t & 31;
  float4 bv = *(const float4*)&bias[c0];
  float acc[2][4];
  #pragma unroll
  for (int i = 0; i < 2; ++i){ acc[i][0]=bv.x; acc[i][1]=bv.y; acc[i][2]=bv.z; acc[i][3]=bv.w; }

  #pragma unroll 8
  for (int h = 0; h < H; ++h) {
    float4 w4 = *(const float4*)&W[h * H + c0];
    float xv0 = xs[rt][h], xv1 = xs[rt + 1][h];
    acc[0][0] = fmaf(xv0, w4.x, acc[0][0]);
    acc[0][1] = fmaf(xv0, w4.y, acc[0][1]);
    acc[0][2] = fmaf(xv0, w4.z, acc[0][2]);
    acc[0][3] = fmaf(xv0, w4.w, acc[0][3]);
    acc[1][0] = fmaf(xv1, w4.x, acc[1][0]);
    acc[1][1] = fmaf(xv1, w4.y, acc[1][1]);
    acc[1][2] = fmaf(xv1, w4.z, acc[1][2]);
    acc[1][3] = fmaf(xv1, w4.w, acc[1][3]);
  }

  if (m == 1 || m == 3) {
    int hh = (m == 1) ? 0 : 1;
    #pragma unroll
    for (int i = 0; i < 2; ++i){
      float4 o; o.x=acc[i][0]; o.y=acc[i][1]; o.z=acc[i][2]; o.w=acc[i][3];
      st[rt + i][lane] = o;
    }
    __syncthreads();
    #pragma unroll
    for (int k = 0; k < 2; ++k) {
      int idx = t + k * 128;
      int q2 = idx >> 3, r = idx & 7;
      g_hvT[hh][q2][r0 + r] = st[r][q2];
    }
  } else {
    float* out = g_pre[m];
    #pragma unroll
    for (int i = 0; i < 2; ++i){
      float4 o; o.x=acc[i][0]; o.y=acc[i][1]; o.z=acc[i][2]; o.w=acc[i][3];
      *(float4*)&out[(r0 + rt + i) * H + c0] = o;
    }
  }
}

// ---------------- P2: action head rows: GeLU -> LN -> @aw2 + ab2 ----------------
__global__ void __launch_bounds__(128) k_action(
    const float* __restrict__ lng, const float* __restrict__ lnb,
    const float* __restrict__ aw2, const float* __restrict__ ab2)
{
  int row = blockIdx.x;
  int h   = threadIdx.x;
  float y = gelu_f(g_pre[0][row * H + h]);

  __shared__ float red1[4], red2[4], ys[H];
  float s1 = wredsum(y);
  float s2 = wredsum(y * y);
  int wid = h >> 5;
  if ((h & 31) == 0){ red1[wid] = s1; red2[wid] = s2; }
  __syncthreads();
  float t1 = red1[0] + red1[1] + red1[2] + red1[3];
  float t2 = red2[0] + red2[1] + red2[2] + red2[3];
  float mean = t1 * (1.0f / H);
  float var  = fmaf(-mean, mean, t2 * (1.0f / H));
  float rstd = rsqa(var + EPS);
  ys[h] = fmaf((y - mean) * rstd, lng[h], lnb[h]);
  __syncthreads();
  if (h < A){
    float acc = ab2[h];
    #pragma unroll 8
    for (int k = 0; k < H; ++k) acc = fmaf(ys[k], aw2[k * A + h], acc);
    g_logits[row * A + h] = acc;
  }
}

// ---------------- P3: action log_softmax over dim 1 (sequence) ----------------
__global__ void __launch_bounds__(512) k_actsm(float* __restrict__ out)
{
  int b = blockIdx.x / A, a = blockIdx.x % A;
  int s = threadIdx.x;
  float v = g_logits[(b * S + s) * A + a];

  __shared__ float red[16];
  __shared__ float bmax_s, bsum_s;
  int wid = s >> 5, lane = s & 31;

  float m = wredmax(v);
  if (lane == 0) red[wid] = m;
  __syncthreads();
  if (s < 32){
    float tt = (s < 16) ? red[s] : -3.4e38f;
    tt = wredmax(tt);
    if (s == 0) bmax_s = tt;
  }
  __syncthreads();
  float bmax = bmax_s;
  float e = ex2a((v - bmax) * LOG2E);
  float sm = wredsum(e);
  __syncthreads();
  if (lane == 0) red[wid] = sm;
  __syncthreads();
  if (s < 32){
    float tt = (s < 16) ? red[s] : 0.0f;
    tt = wredsum(tt);
    if (s == 0) bsum_s = tt;
  }
  __syncthreads();
  out[(b * S + s) * A + a] = v - bmax - lg2a(bsum_s) * LN2;
}

// ---------------- P4: pointer heads (f32x2 + HW tanh, 4 i-rows/warp) ---------
// grid (S/4, B, 2) = 512 CTAs, block 256 = 8 j-groups of 64 j each.
// Warp g owns j in [g*64, g*64+64) (2 tiles of 32) x ALL 4 CTA i-rows:
// each hv LDG.128 feeds 4 gelu chains (64 packed fma / load).
__global__ void __launch_bounds__(256, 4) k_ptr(
    const float* __restrict__ lg, const float* __restrict__ lb,
    const float* __restrict__ lpw, const float* __restrict__ lpb,
    const float* __restrict__ rg, const float* __restrict__ rb,
    const float* __restrict__ rpw, const float* __restrict__ rpb,
    float* __restrict__ out)
{
  int head = blockIdx.z, b = blockIdx.y;
  int i0 = blockIdx.x * 4;
  const float* gv = head ? rg  : lg;
  const float* bv = head ? rb  : lb;
  const float* pw = head ? rpw : lpw;
  const float* pb = head ? rpb : lpb;
  const float* hd = g_pre[2 + 2 * head] + b * S * H;   // indexed by i

  __shared__ __align__(16) float hds[4][H];
  __shared__ __align__(16) float wgh[H];
  __shared__ float redc[4][2];
  __shared__ float cc2[2];
  __shared__ float gmaxs[8][4], gsums[8][4];

  int tid  = threadIdx.x;
  int wid  = tid >> 5, lane = tid & 31;
  int g    = wid;             // j-group (0..7), 64 j each

  // folded weights: wgh = g*pw ; c1 = sum(g*pw) ; c2 = sum(b*pw) + pb
  if (tid < 128) {
    float p  = pw[tid];
    float wg = gv[tid] * p;
    float tb = bv[tid] * p;
    wgh[tid] = wg;
    float r1 = wredsum(wg), r2 = wredsum(tb);
    if (lane == 0){ redc[wid][0] = r1; redc[wid][1] = r2; }
  }
  for (int idx = tid; idx < 4 * H; idx += 256)
    hds[idx >> 7][idx & (H - 1)] = hd[(i0 + (idx >> 7)) * H + (idx & (H - 1))];
  __syncthreads();
  if (tid == 0){
    cc2[0] = redc[0][0] + redc[1][0] + redc[2][0] + redc[3][0];
    cc2[1] = redc[0][1] + redc[1][1] + redc[2][1] + redc[3][1] + pb[0];
  }
  __syncthreads();
  float c1 = cc2[0], c2 = cc2[1];

  const ull K0p = pk2(TK0, TK0);
  const ull K1p = pk2(TK1, TK1);
  const ull* wr = (const ull*)&wgh[0];

  float sc[4][2];   // [i-row][tile]

  #pragma unroll
  for (int tile = 0; tile < 2; ++tile) {
    int jb = g * 64 + tile * 32;
    const ulonglong2* ap = (const ulonglong2*)&g_hvT[head][0][b * S + jb + lane];

    ull s1[4], s2[4], s3[4];
    #pragma unroll
    for (int r = 0; r < 4; ++r){ s1[r] = 0; s2[r] = 0; s3[r] = 0; }

    #pragma unroll 8
    for (int q2 = 0; q2 < 32; ++q2) {
      ulonglong2 a2 = ap[q2 * BS];
      #pragma unroll
      for (int half = 0; half < 2; ++half) {
        ull a = half ? a2.y : a2.x;
        ull w = wr[q2 * 2 + half];
        #pragma unroll
        for (int r = 0; r < 4; ++r) {
          ull d  = ((const ull*)&hds[r][0])[q2 * 2 + half];
          ull x  = add2(a, d);
          ull x2 = mul2(x, x);
          ull p  = fma2(K1p, x2, K0p);
          ull u  = mul2(x, p);
          float u0f, u1f; upk2(u, u0f, u1f);
          ull t  = pk2(tanha(u0f), tanha(u1f));
          ull z  = fma2(x, t, x);          // z = 2*gelu(x)
          s1[r] = add2(s1[r], z);
          s2[r] = fma2(z, z, s2[r]);
          s3[r] = fma2(z, w, s3[r]);
        }
      }
    }
    #pragma unroll
    for (int r = 0; r < 4; ++r) {
      float a0,a1,q0,q1,d0,d1;
      upk2(s1[r], a0, a1); upk2(s2[r], q0, q1); upk2(s3[r], d0, d1);
      float t1 = a0 + a1, t2 = q0 + q1, t3 = d0 + d1;
      float mean = t1 * (0.5f / H);                       // sum(y)/H, y = z/2
      float var  = fmaf(-mean, mean, t2 * (0.25f / H));
      float rstd = rsqa(var + EPS);
      sc[r][tile] = fmaf(rstd, fmaf(-mean, c1, 0.5f * t3), c2);
    }
  }

  // log_softmax over j: combine 8 j-groups per i-row
  float lm[4];
  #pragma unroll
  for (int r = 0; r < 4; ++r) {
    lm[r] = wredmax(fmaxf(sc[r][0], sc[r][1]));
    if (lane == 0) gmaxs[g][r] = lm[r];
  }
  __syncthreads();
  float mrow[4], ls[4];
  #pragma unroll
  for (int r = 0; r < 4; ++r) {
    float m = gmaxs[0][r];
    #pragma unroll
    for (int gg = 1; gg < 8; ++gg) m = fmaxf(m, gmaxs[gg][r]);
    mrow[r] = m;
    float s = ex2a((sc[r][0] - m) * LOG2E) + ex2a((sc[r][1] - m) * LOG2E);
    ls[r] = wredsum(s);
    if (lane == 0) gsums[g][r] = ls[r];
  }
  __syncthreads();
  float* obase = out + B * S * A + head * (B * S * S);
  #pragma unroll
  for (int r = 0; r < 4; ++r) {
    float s = gsums[0][r];
    #pragma unroll
    for (int gg = 1; gg < 8; ++gg) s += gsums[gg][r];
    float lse = lg2a(s) * LN2;
    float* orow = obase + (b * S + i0 + r) * S + g * 64;
    orow[lane]      = sc[r][0] - mrow[r] - lse;
    orow[32 + lane] = sc[r][1] - mrow[r] - lse;
  }
}

extern "C" void kernel_launch(void* const* d_in, const int* in_sizes, int n_in,
                              void* d_out, int out_size)
{
  (void)in_sizes; (void)n_in; (void)out_size;
  const float* hiddens = (const float*)d_in[0];
  const float* aw1     = (const float*)d_in[1];
  const float* ab1     = (const float*)d_in[2];
  const float* a_ln_g  = (const float*)d_in[3];
  const float* a_ln_b  = (const float*)d_in[4];
  const float* aw2     = (const float*)d_in[5];
  const float* ab2     = (const float*)d_in[6];
  const float* lhid_w  = (const float*)d_in[7];
  const float* lhid_b  = (const float*)d_in[8];
  const float* lhead_w = (const float*)d_in[9];
  const float* lhead_b = (const float*)d_in[10];
  const float* l_ln_g  = (const float*)d_in[11];
  const float* l_ln_b  = (const float*)d_in[12];
  const float* l_proj_w= (const float*)d_in[13];
  const float* l_proj_b= (const float*)d_in[14];
  const float* rhid_w  = (const float*)d_in[15];
  const float* rhid_b  = (const float*)d_in[16];
  const float* rhead_w = (const float*)d_in[17];
  const float* rhead_b = (const float*)d_in[18];
  const float* r_ln_g  = (const float*)d_in[19];
  const float* r_ln_b  = (const float*)d_in[20];
  const float* r_proj_w= (const float*)d_in[21];
  const float* r_proj_b= (const float*)d_in[22];
  float* out = (float*)d_out;

  k_gemm<<<dim3(BS / 8, 5), 128>>>(hiddens,
      aw1, ab1, lhid_w, lhid_b, lhead_w, lhead_b, rhid_w, rhid_b, rhead_w, rhead_b);
  k_action<<<BS, 128>>>(a_ln_g, a_ln_b, aw2, ab2);
  k_actsm<<<B * A, 512>>>(out);
  k_ptr<<<dim3(S / 4, B, 2), 256>>>(l_ln_g, l_ln_b, l_proj_w, l_proj_b,
                                    r_ln_g, r_ln_b, r_proj_w, r_proj_b, out);
}